// round 8
// baseline (speedup 1.0000x reference)
#include <cuda_runtime.h>
#include <cuda_bf16.h>
#include <cstdint>

typedef unsigned long long u64;

#define BB 32
#define TT 256
#define II 128
#define HH 128
#define GG 512   // 4*H
#define CC 100
#define WS_PAD 132

// phase 2: per-row split of the 64 k-pairs (one row per thread, 512 threads)
#define RREG 46                 // u64 pairs in registers (k = 0..91)
#define RSM  (64 - RREG)        // 18 pairs from smem    (k = 92..127)
#define RSMC (RSM / 2)          // 9 ulonglong2 chunks

// ---------------- scratch (device globals; no allocation allowed) ----------
__device__ float g_gatesx[TT * BB * GG];      // [t][b][g]
__device__ float g_hist[(TT + 1) * BB * HH];  // [j][b][u], j=1..256 = h_1..h_256
__device__ float g_attn[BB * HH];
__device__ float g_q[BB * HH];                // q = h_T @ w1_top

__device__ __forceinline__ void fma2(u64 &acc, u64 a, u64 b) {
    asm("fma.rn.f32x2 %0, %1, %2, %0;" : "+l"(acc) : "l"(a), "l"(b));
}
__device__ __forceinline__ float sum2(u64 v) {
    float lo, hi;
    asm("mov.b64 {%0,%1}, %2;" : "=f"(lo), "=f"(hi) : "l"(v));
    return lo + hi;
}
// fast activations via MUFU ex2/rcp (~1e-7 abs error; rel_err margin is 3.7e-7 vs 1e-3)
__device__ __forceinline__ float fast_tanh(float x) {
    float e, r;
    asm("ex2.approx.f32 %0, %1;" : "=f"(e) : "f"(2.8853900817779268f * x)); // e^(2x)
    asm("rcp.approx.f32 %0, %1;" : "=f"(r) : "f"(e + 1.0f));
    return fmaf(-2.0f, r, 1.0f);
}

// ---------------------------------------------------------------------------
// Phase 1: gates_x[t][b][g] = x[b,t,:] . w_ih[g,:] + b_ih[g] + b_hh[g]
// grid (T, 4) x 256 threads.
// ---------------------------------------------------------------------------
__global__ void __launch_bounds__(256, 2) phase1_kernel(
    const float* __restrict__ x, const float* __restrict__ w_ih,
    const float* __restrict__ b_ih, const float* __restrict__ b_hh)
{
    extern __shared__ float sm[];
    float* x_s = sm;                 // [32][128]
    float* ws  = sm + BB * II;       // [128][WS_PAD]
    const int t   = blockIdx.x;
    const int gq  = blockIdx.y;      // 0..3: which 128-gate tile
    const int tid = threadIdx.x;

    for (int i = tid; i < BB * II; i += 256) {
        int b = i >> 7, k = i & 127;
        x_s[i] = x[(b * TT + t) * II + k];
    }
    const float* wsrc = w_ih + gq * 128 * II;
    for (int i = tid; i < 128 * II; i += 256) {
        int gl = i >> 7, k = i & 127;
        ws[gl * WS_PAD + k] = wsrc[i];
    }
    if (t == 0 && gq == 0) {   // re-zero attention accumulator every launch
        for (int i = tid; i < BB * HH; i += 256) g_attn[i] = 0.0f;
    }
    __syncthreads();

    const int gl   = tid & 127;
    const int half = tid >> 7;
    const int g    = gq * 128 + gl;
    const float bias = b_ih[g] + b_hh[g];
    const float* wrow = ws + gl * WS_PAD;

    for (int bq = 0; bq < 2; bq++) {
        const int b0 = half * 16 + bq * 8;
        u64 acc[8];
        #pragma unroll
        for (int j = 0; j < 8; j++) acc[j] = 0ull;
        #pragma unroll
        for (int k0 = 0; k0 < II; k0 += 4) {
            ulonglong2 w = *(const ulonglong2*)(wrow + k0);
            #pragma unroll
            for (int j = 0; j < 8; j++) {
                ulonglong2 xv = *(const ulonglong2*)(x_s + (b0 + j) * II + k0);
                fma2(acc[j], w.x, xv.x);
                fma2(acc[j], w.y, xv.y);
            }
        }
        #pragma unroll
        for (int j = 0; j < 8; j++)
            g_gatesx[(t * BB + b0 + j) * GG + g] = sum2(acc[j]) + bias;
    }
}

// ---------------------------------------------------------------------------
// Phase 2: LSTM recurrence. 32 blocks (one per batch) x 512 threads, ONE gate
// row per thread. Unit u = tid>>2, gate gi = tid&3 (0:i 1:f 2:g 3:o) -> the
// four gates of unit u sit on 4 ADJACENT LANES. Gate allgather = 3 shfl_xor;
// quad-leader (gi==0) updates c and h. ONE __syncthreads per step.
// Weights: k=0..91 register-resident (92 regs, fits the 128-reg cap with
// slack); k=92..127 streamed from smem as conflict-free LDS.128.
// ---------------------------------------------------------------------------
__global__ void __launch_bounds__(512, 1) phase2_kernel(const float* __restrict__ w_hh)
{
    extern __shared__ float sm2[];
    float* h_buf = sm2;                              // [2][128]
    ulonglong2* ws2 = (ulonglong2*)(sm2 + 256);      // [RSMC][512]
    const int b   = blockIdx.x;
    const int tid = threadIdx.x;
    const int u   = tid >> 2;
    const int gi  = tid & 3;
    const int row = gi * HH + u;

    const float* wrow = w_hh + row * HH;
    u64 wr[RREG];
    #pragma unroll
    for (int i = 0; i < RREG; i++) wr[i] = *(const u64*)(wrow + 2 * i);
    #pragma unroll
    for (int j = 0; j < RSMC; j++)
        ws2[j * 512 + tid] = *(const ulonglong2*)(wrow + 2 * RREG + 4 * j);

    if (tid < 256) h_buf[tid] = 0.0f;
    float c = 0.0f;

    // branch-free activation constants: act = A * 1/(2^(k*x)+1) + B
    //   sigmoid: k=-log2(e), A=1, B=0 ; tanh(g-gate): k=2*log2(e), A=-2, B=1
    const bool  isg  = (gi == 2);
    const float kmul = isg ?  2.8853900817779268f : -1.4426950408889634f;
    const float Amul = isg ? -2.0f : 1.0f;
    const float Badd = isg ?  1.0f : 0.0f;
    __syncthreads();

    const int stride_t = BB * GG;
    const float* gxp = g_gatesx + b * GG + row;
    float gxn = gxp[0];

    for (int t = 0; t < TT; t++) {
        const int p = t & 1;
        float gx = gxn;
        if (t + 1 < TT) gxn = gxp[(t + 1) * stride_t];

        const ulonglong2* h4 = (const ulonglong2*)(h_buf + p * 128);  // 32 bcast chunks
        u64 a0 = 0ull, a1 = 0ull;
        #pragma unroll
        for (int i = 0; i < RREG / 2; i++) {          // k = 0 .. 91
            ulonglong2 hv = h4[i];
            fma2(a0, wr[2 * i],     hv.x);
            fma2(a1, wr[2 * i + 1], hv.y);
        }
        #pragma unroll
        for (int j = 0; j < RSMC; j++) {              // k = 92 .. 127
            ulonglong2 hv = h4[RREG / 2 + j];
            ulonglong2 w  = ws2[j * 512 + tid];
            fma2(a0, w.x, hv.x);
            fma2(a1, w.y, hv.y);
        }

        float gate = gx + sum2(a0) + sum2(a1);
        float e, r;
        asm("ex2.approx.f32 %0, %1;" : "=f"(e) : "f"(kmul * gate));
        asm("rcp.approx.f32 %0, %1;" : "=f"(r) : "f"(e + 1.0f));
        float a = fmaf(Amul, r, Badd);                // activated gate

        // allgather the quad's 4 gates (lanes 4u..4u+3): 3 butterflies
        float x1 = __shfl_xor_sync(0xffffffffu, a, 1);   // partner gate
        float x2 = __shfl_xor_sync(0xffffffffu, a, 2);
        float x3 = __shfl_xor_sync(0xffffffffu, x1, 2);

        if (gi == 0) {
            // lane 4u: a = sig(i), x1 = sig(f), x2 = tanh(g), x3 = sig(o)
            c = x1 * c + a * x2;
            float hv = x3 * fast_tanh(c);
            h_buf[(1 - p) * 128 + u] = hv;
            g_hist[(t + 1) * (BB * HH) + b * HH + u] = hv;
        }
        __syncthreads();
    }
}

// ---------------------------------------------------------------------------
// Phase q: g_q[b][n] = sum_k h_T[k] * w1[k][n]   (w1 top half)
// ---------------------------------------------------------------------------
__global__ void __launch_bounds__(128, 8) phaseq_kernel(const float* __restrict__ w1)
{
    __shared__ float hf[HH];
    const int b = blockIdx.x, n = threadIdx.x;
    hf[n] = g_hist[TT * (BB * HH) + b * HH + n];
    __syncthreads();
    float q = 0.0f;
    #pragma unroll 4
    for (int k = 0; k < HH; k++) q += hf[k] * w1[k * HH + n];
    g_q[b * HH + n] = q;
}

// ---------------------------------------------------------------------------
// Phase 3a: final attention over memory h_1..h_255.
//   p_j[n] = sum_k h_j[k] * w1[H+k][n]
//   s_j    = sum_n w2[n] * tanh(q[b][n] + p_j[n])
//   attn[b][n] += sum_j s_j * h_j[n]
// grid (B, 8) x 256 threads; each block covers 32 j's in 4 tiles of 8.
// w1 bottom half TRANSPOSED in smem ([n][k], padded 132) so the k-loop runs
// on LDS.128 for both operands; packed fma2 accumulate.
// ---------------------------------------------------------------------------
__global__ void __launch_bounds__(256, 1) phase3a_kernel(
    const float* __restrict__ w1, const float* __restrict__ w2)
{
    extern __shared__ float sm3[];
    float* wsT  = sm3;                        // [128 n][WS_PAD k]
    float* w2_s = wsT + 128 * WS_PAD;         // [128]
    float* hj_s = w2_s + 128;                 // [8][128]
    float* red  = hj_s + 8 * 128;             // [8][4]
    float* s_t  = red + 32;                   // [8]
    const int b   = blockIdx.x;
    const int jc  = blockIdx.y;
    const int tid = threadIdx.x;
    const int n    = tid & 127;
    const int half = tid >> 7;
    const int lane = tid & 31;
    const int wl   = (tid >> 5) & 3;

    const float* w1b = w1 + HH * HH;          // bottom half [k][n]
    for (int i = tid; i < HH * HH; i += 256) {
        int k = i >> 7, nn = i & 127;         // coalesced read, transposed write
        wsT[nn * WS_PAD + k] = w1b[i];
    }
    if (tid < 128) w2_s[tid] = w2[tid];
    __syncthreads();

    const float q   = g_q[b * HH + n];
    const float w2n = w2_s[n];

    float accA = 0.0f;
    const int j0 = 1 + jc * 32;
    const int jb = half * 4;
    const float* wrow = wsT + n * WS_PAD;

    for (int tile = 0; tile < 4; tile++) {
        int jt = j0 + tile * 8;
        {   // stage 8 h-rows as float4 (256 threads x 1 float4)
            int jj = tid >> 5, k4 = (tid & 31) * 4;
            int j = jt + jj;
            float4 v = make_float4(0.f, 0.f, 0.f, 0.f);
            if (j <= TT - 1) v = *(const float4*)(g_hist + j * (BB * HH) + b * HH + k4);
            *(float4*)(hj_s + jj * 128 + k4) = v;
        }
        __syncthreads();

        u64 p0 = 0ull, p1 = 0ull, p2 = 0ull, p3 = 0ull;
        #pragma unroll 8
        for (int k0 = 0; k0 < HH; k0 += 4) {
            ulonglong2 w  = *(const ulonglong2*)(wrow + k0);
            ulonglong2 h0 = *(const ulonglong2*)(hj_s + (jb + 0) * 128 + k0);
            ulonglong2 h1 = *(const ulonglong2*)(hj_s + (jb + 1) * 128 + k0);
            ulonglong2 h2 = *(const ulonglong2*)(hj_s + (jb + 2) * 128 + k0);
            ulonglong2 h3 = *(const ulonglong2*)(hj_s + (jb + 3) * 128 + k0);
            fma2(p0, w.x, h0.x); fma2(p0, w.y, h0.y);
            fma2(p1, w.x, h1.x); fma2(p1, w.y, h1.y);
            fma2(p2, w.x, h2.x); fma2(p2, w.y, h2.y);
            fma2(p3, w.x, h3.x); fma2(p3, w.y, h3.y);
        }
        float sv[4];
        sv[0] = w2n * fast_tanh(q + sum2(p0));
        sv[1] = w2n * fast_tanh(q + sum2(p1));
        sv[2] = w2n * fast_tanh(q + sum2(p2));
        sv[3] = w2n * fast_tanh(q + sum2(p3));
        #pragma unroll
        for (int jj = 0; jj < 4; jj++) {
            float v = sv[jj];
            v += __shfl_down_sync(0xffffffffu, v, 16);
            v += __shfl_down_sync(0xffffffffu, v, 8);
            v += __shfl_down_sync(0xffffffffu, v, 4);
            v += __shfl_down_sync(0xffffffffu, v, 2);
            v += __shfl_down_sync(0xffffffffu, v, 1);
            if (lane == 0) red[(half * 4 + jj) * 4 + wl] = v;
        }
        __syncthreads();
        if (tid < 8)
            s_t[tid] = red[tid * 4 + 0] + red[tid * 4 + 1] + red[tid * 4 + 2] + red[tid * 4 + 3];
        __syncthreads();

        accA += s_t[jb + 0] * hj_s[(jb + 0) * 128 + n]
              + s_t[jb + 1] * hj_s[(jb + 1) * 128 + n]
              + s_t[jb + 2] * hj_s[(jb + 2) * 128 + n]
              + s_t[jb + 3] * hj_s[(jb + 3) * 128 + n];
        __syncthreads();   // protect hj_s / red / s_t before next tile
    }
    atomicAdd(&g_attn[b * HH + n], accA);
}

// ---------------------------------------------------------------------------
// Phase 3b: out[b] = (h_T + attn[b]) @ w_fc^T + b_fc      (32 x 100 output)
// ---------------------------------------------------------------------------
__global__ void __launch_bounds__(128, 8) phase3b_kernel(
    const float* __restrict__ w_fc, const float* __restrict__ b_fc,
    float* __restrict__ out)
{
    __shared__ float v_s[HH];
    const int b = blockIdx.x, tid = threadIdx.x;
    v_s[tid] = g_hist[TT * (BB * HH) + b * HH + tid] + g_attn[b * HH + tid];
    __syncthreads();
    if (tid < CC) {
        float acc = b_fc[tid];
        const float4* wr4 = (const float4*)(w_fc + tid * HH);
        const float4* v4  = (const float4*)v_s;
        #pragma unroll
        for (int k4 = 0; k4 < HH / 4; k4++) {
            float4 w = wr4[k4];
            float4 v = v4[k4];
            acc += w.x * v.x + w.y * v.y + w.z * v.z + w.w * v.w;
        }
        out[b * CC + tid] = acc;
    }
}

// ---------------------------------------------------------------------------
extern "C" void kernel_launch(void* const* d_in, const int* in_sizes, int n_in,
                              void* d_out, int out_size)
{
    const float* x    = (const float*)d_in[0];
    const float* w_ih = (const float*)d_in[1];
    const float* b_ih = (const float*)d_in[2];
    const float* w_hh = (const float*)d_in[3];
    const float* b_hh = (const float*)d_in[4];
    const float* w1   = (const float*)d_in[5];
    const float* w2   = (const float*)d_in[6];
    const float* w_fc = (const float*)d_in[7];
    const float* b_fc = (const float*)d_in[8];
    float* out = (float*)d_out;

    const int SM1 = (BB * II + 128 * WS_PAD) * (int)sizeof(float);                 // ~84 KB
    const int SM2 = 256 * (int)sizeof(float) + RSMC * 512 * (int)sizeof(ulonglong2); // ~74.8 KB
    const int SM3 = (128 * WS_PAD + 128 + 8 * 128 + 32 + 8) * (int)sizeof(float);  // ~72.4 KB

    cudaFuncSetAttribute(phase1_kernel,  cudaFuncAttributeMaxDynamicSharedMemorySize, SM1);
    cudaFuncSetAttribute(phase2_kernel,  cudaFuncAttributeMaxDynamicSharedMemorySize, SM2);
    cudaFuncSetAttribute(phase3a_kernel, cudaFuncAttributeMaxDynamicSharedMemorySize, SM3);

    phase1_kernel <<<dim3(TT, 4), 256, SM1>>>(x, w_ih, b_ih, b_hh);
    phase2_kernel <<<BB, 512, SM2>>>(w_hh);
    phaseq_kernel <<<BB, HH>>>(w1);
    phase3a_kernel<<<dim3(BB, 8), 256, SM3>>>(w1, w2);
    phase3b_kernel<<<BB, HH>>>(w_fc, b_fc, out);
}

// round 9
// speedup vs baseline: 1.1337x; 1.1337x over previous
#include <cuda_runtime.h>
#include <cuda_bf16.h>
#include <cstdint>

typedef unsigned long long u64;

#define BB 32
#define TT 256
#define II 128
#define HH 128
#define GG 512   // 4*H
#define CC 100
#define WS_PAD 132

// phase 2: per gate-row split of the 64 k-pairs (2 rows per thread, 256 thr)
#define RREG 46                 // u64 pairs in registers per row (k = 0..91)
#define RSM  (64 - RREG)        // 18 pairs per row from smem     (k = 92..127)
#define RSMC (RSM / 2)          // 9 ulonglong2 chunks per row

// ---------------- scratch (device globals; no allocation allowed) ----------
__device__ float g_gatesx[(TT + 1) * BB * GG]; // [t][b][g], +1 step pad for branchless prefetch
__device__ float g_hist[(TT + 1) * BB * HH];   // [j][b][u], j=1..256 = h_1..h_256
__device__ float g_attn[BB * HH];
__device__ float g_q[BB * HH];                 // q = h_T @ w1_top

__device__ __forceinline__ void fma2(u64 &acc, u64 a, u64 b) {
    asm("fma.rn.f32x2 %0, %1, %2, %0;" : "+l"(acc) : "l"(a), "l"(b));
}
__device__ __forceinline__ float sum2(u64 v) {
    float lo, hi;
    asm("mov.b64 {%0,%1}, %2;" : "=f"(lo), "=f"(hi) : "l"(v));
    return lo + hi;
}
// fast activations via MUFU ex2/rcp (~1e-7 abs err; margin vs 1e-3 gate is huge)
__device__ __forceinline__ float fast_sig(float x) {
    float e, r;
    asm("ex2.approx.f32 %0, %1;" : "=f"(e) : "f"(-1.4426950408889634f * x)); // e^-x
    asm("rcp.approx.f32 %0, %1;" : "=f"(r) : "f"(e + 1.0f));
    return r;
}
__device__ __forceinline__ float fast_tanh(float x) {
    float e, r;
    asm("ex2.approx.f32 %0, %1;" : "=f"(e) : "f"(2.8853900817779268f * x));  // e^(2x)
    asm("rcp.approx.f32 %0, %1;" : "=f"(r) : "f"(e + 1.0f));
    return fmaf(-2.0f, r, 1.0f);
}

// ---------------------------------------------------------------------------
// Phase 1: gates_x[t][b][g] = x[b,t,:] . w_ih[g,:] + b_ih[g] + b_hh[g]
// grid (T, 4) x 256 threads.
// ---------------------------------------------------------------------------
__global__ void __launch_bounds__(256, 2) phase1_kernel(
    const float* __restrict__ x, const float* __restrict__ w_ih,
    const float* __restrict__ b_ih, const float* __restrict__ b_hh)
{
    extern __shared__ float sm[];
    float* x_s = sm;                 // [32][128]
    float* ws  = sm + BB * II;       // [128][WS_PAD]
    const int t   = blockIdx.x;
    const int gq  = blockIdx.y;      // 0..3: which 128-gate tile
    const int tid = threadIdx.x;

    for (int i = tid; i < BB * II; i += 256) {
        int b = i >> 7, k = i & 127;
        x_s[i] = x[(b * TT + t) * II + k];
    }
    const float* wsrc = w_ih + gq * 128 * II;
    for (int i = tid; i < 128 * II; i += 256) {
        int gl = i >> 7, k = i & 127;
        ws[gl * WS_PAD + k] = wsrc[i];
    }
    if (t == 0 && gq == 0) {   // re-zero attention accumulator every launch
        for (int i = tid; i < BB * HH; i += 256) g_attn[i] = 0.0f;
    }
    __syncthreads();

    const int gl   = tid & 127;
    const int half = tid >> 7;
    const int g    = gq * 128 + gl;
    const float bias = b_ih[g] + b_hh[g];
    const float* wrow = ws + gl * WS_PAD;

    for (int bq = 0; bq < 2; bq++) {
        const int b0 = half * 16 + bq * 8;
        u64 acc[8];
        #pragma unroll
        for (int j = 0; j < 8; j++) acc[j] = 0ull;
        #pragma unroll
        for (int k0 = 0; k0 < II; k0 += 4) {
            ulonglong2 w = *(const ulonglong2*)(wrow + k0);
            #pragma unroll
            for (int j = 0; j < 8; j++) {
                ulonglong2 xv = *(const ulonglong2*)(x_s + (b0 + j) * II + k0);
                fma2(acc[j], w.x, xv.x);
                fma2(acc[j], w.y, xv.y);
            }
        }
        #pragma unroll
        for (int j = 0; j < 8; j++)
            g_gatesx[(t * BB + b0 + j) * GG + g] = sum2(acc[j]) + bias;
    }
}

// ---------------------------------------------------------------------------
// Phase 2: LSTM recurrence. 32 blocks (one per batch) x 256 threads; each
// thread owns TWO gate rows: rowA = tid (i|f), rowB = tid + 256 (g|o).
//   tid<128  : rowA = i-gate(u=tid),     rowB = g-gate(u=tid)
//   tid>=128 : rowA = f-gate(u=tid-128), rowB = o-gate(u=tid-128)
// Gate exchange via act_s smem (proven-best R4 tail); h double-buffered;
// two __syncthreads per step. Weights k=0..91 register-resident per row
// (184 regs, ~40 slack for LDS pipelining); k=92..127 streamed from smem
// as conflict-free [chunk][tid] ulonglong2 (LDS.128).
// ---------------------------------------------------------------------------
__global__ void __launch_bounds__(256, 1) phase2_kernel(const float* __restrict__ w_hh)
{
    extern __shared__ float sm2[];
    float* h_buf = sm2;                              // [2][128]
    float* act_s = sm2 + 256;                        // [512]
    ulonglong2* ws2 = (ulonglong2*)(sm2 + 768);      // [2*RSMC][256]
    const int b   = blockIdx.x;
    const int tid = threadIdx.x;

    const float* wA = w_hh + tid * HH;               // i|f row
    const float* wB = w_hh + (tid + 256) * HH;       // g|o row
    u64 wrA[RREG], wrB[RREG];
    #pragma unroll
    for (int i = 0; i < RREG; i++) {
        wrA[i] = *(const u64*)(wA + 2 * i);
        wrB[i] = *(const u64*)(wB + 2 * i);
    }
    #pragma unroll
    for (int j = 0; j < RSMC; j++) {
        ws2[j * 256 + tid]          = *(const ulonglong2*)(wA + 2 * RREG + 4 * j);
        ws2[(RSMC + j) * 256 + tid] = *(const ulonglong2*)(wB + 2 * RREG + 4 * j);
    }

    if (tid < 256) h_buf[tid] = 0.0f;   // zero both h buffers
    float c = 0.0f;
    __syncthreads();

    const int stride_t = BB * GG;
    const float* gxpA = g_gatesx + b * GG + tid;
    const float* gxpB = gxpA + 256;
    float gxnA = gxpA[0];
    float gxnB = gxpB[0];

    for (int t = 0; t < TT; t++) {
        const int p = t & 1;
        float gxA = gxnA, gxB = gxnB;
        gxnA = gxpA[(t + 1) * stride_t];   // pad row makes t=255 read safe
        gxnB = gxpB[(t + 1) * stride_t];

        const ulonglong2* h4 = (const ulonglong2*)(h_buf + p * 128);  // 32 bcast chunks

        u64 a0 = 0ull, a1 = 0ull, b0 = 0ull, b1 = 0ull;
        #pragma unroll
        for (int i = 0; i < RREG / 2; i++) {          // k = 0 .. 91
            ulonglong2 hv = h4[i];
            fma2(a0, wrA[2 * i],     hv.x);
            fma2(a1, wrA[2 * i + 1], hv.y);
            fma2(b0, wrB[2 * i],     hv.x);
            fma2(b1, wrB[2 * i + 1], hv.y);
        }
        #pragma unroll
        for (int j = 0; j < RSMC; j++) {              // k = 92 .. 127
            ulonglong2 hv = h4[RREG / 2 + j];
            ulonglong2 wa = ws2[j * 256 + tid];
            ulonglong2 wb = ws2[(RSMC + j) * 256 + tid];
            fma2(a0, wa.x, hv.x);
            fma2(a1, wa.y, hv.y);
            fma2(b0, wb.x, hv.x);
            fma2(b1, wb.y, hv.y);
        }

        float gateA = gxA + sum2(a0) + sum2(a1);
        float gateB = gxB + sum2(b0) + sum2(b1);
        float aA = fast_sig(gateA);                   // i (tid<128) or f
        float aB = (tid < 128) ? fast_tanh(gateB)     // g
                               : fast_sig(gateB);     // o
        act_s[tid]       = aA;
        act_s[256 + tid] = aB;
        __syncthreads();                              // gates ready; h reads done

        if (tid < 128) {
            float af = act_s[128 + tid];
            float ao = act_s[384 + tid];
            c = af * c + aA * aB;                     // sig(f)*c + sig(i)*tanh(g)
            float hv = ao * fast_tanh(c);
            h_buf[(1 - p) * 128 + tid] = hv;
            g_hist[(t + 1) * (BB * HH) + b * HH + tid] = hv;
        }
        __syncthreads();                              // new h visible
    }
}

// ---------------------------------------------------------------------------
// Phase q: g_q[b][n] = sum_k h_T[k] * w1[k][n]   (w1 top half)
// ---------------------------------------------------------------------------
__global__ void __launch_bounds__(128, 8) phaseq_kernel(const float* __restrict__ w1)
{
    __shared__ float hf[HH];
    const int b = blockIdx.x, n = threadIdx.x;
    hf[n] = g_hist[TT * (BB * HH) + b * HH + n];
    __syncthreads();
    float q = 0.0f;
    #pragma unroll 4
    for (int k = 0; k < HH; k++) q += hf[k] * w1[k * HH + n];
    g_q[b * HH + n] = q;
}

// ---------------------------------------------------------------------------
// Phase 3a: final attention over memory h_1..h_255.
//   p_j[n] = sum_k h_j[k] * w1[H+k][n]
//   s_j    = sum_n w2[n] * tanh(q[b][n] + p_j[n])
//   attn[b][n] += sum_j s_j * h_j[n]
// grid (B, 8) x 256 threads; each block covers 32 j's in 4 tiles of 8.
// w1 bottom half transposed in smem ([n][k], pad 132): LDS.128 both operands.
// ---------------------------------------------------------------------------
__global__ void __launch_bounds__(256, 1) phase3a_kernel(
    const float* __restrict__ w1, const float* __restrict__ w2)
{
    extern __shared__ float sm3[];
    float* wsT  = sm3;                        // [128 n][WS_PAD k]
    float* w2_s = wsT + 128 * WS_PAD;         // [128]
    float* hj_s = w2_s + 128;                 // [8][128]
    float* red  = hj_s + 8 * 128;             // [8][4]
    float* s_t  = red + 32;                   // [8]
    const int b   = blockIdx.x;
    const int jc  = blockIdx.y;
    const int tid = threadIdx.x;
    const int n    = tid & 127;
    const int half = tid >> 7;
    const int lane = tid & 31;
    const int wl   = (tid >> 5) & 3;

    const float* w1b = w1 + HH * HH;          // bottom half [k][n]
    for (int i = tid; i < HH * HH; i += 256) {
        int k = i >> 7, nn = i & 127;         // coalesced read, transposed write
        wsT[nn * WS_PAD + k] = w1b[i];
    }
    if (tid < 128) w2_s[tid] = w2[tid];
    __syncthreads();

    const float q   = g_q[b * HH + n];
    const float w2n = w2_s[n];

    float accA = 0.0f;
    const int j0 = 1 + jc * 32;
    const int jb = half * 4;
    const float* wrow = wsT + n * WS_PAD;

    for (int tile = 0; tile < 4; tile++) {
        int jt = j0 + tile * 8;
        {   // stage 8 h-rows as float4 (256 threads x 1 float4)
            int jj = tid >> 5, k4 = (tid & 31) * 4;
            int j = jt + jj;
            float4 v = make_float4(0.f, 0.f, 0.f, 0.f);
            if (j <= TT - 1) v = *(const float4*)(g_hist + j * (BB * HH) + b * HH + k4);
            *(float4*)(hj_s + jj * 128 + k4) = v;
        }
        __syncthreads();

        u64 p0 = 0ull, p1 = 0ull, p2 = 0ull, p3 = 0ull;
        #pragma unroll 8
        for (int k0 = 0; k0 < HH; k0 += 4) {
            ulonglong2 w  = *(const ulonglong2*)(wrow + k0);
            ulonglong2 h0 = *(const ulonglong2*)(hj_s + (jb + 0) * 128 + k0);
            ulonglong2 h1 = *(const ulonglong2*)(hj_s + (jb + 1) * 128 + k0);
            ulonglong2 h2 = *(const ulonglong2*)(hj_s + (jb + 2) * 128 + k0);
            ulonglong2 h3 = *(const ulonglong2*)(hj_s + (jb + 3) * 128 + k0);
            fma2(p0, w.x, h0.x); fma2(p0, w.y, h0.y);
            fma2(p1, w.x, h1.x); fma2(p1, w.y, h1.y);
            fma2(p2, w.x, h2.x); fma2(p2, w.y, h2.y);
            fma2(p3, w.x, h3.x); fma2(p3, w.y, h3.y);
        }
        float sv[4];
        sv[0] = w2n * fast_tanh(q + sum2(p0));
        sv[1] = w2n * fast_tanh(q + sum2(p1));
        sv[2] = w2n * fast_tanh(q + sum2(p2));
        sv[3] = w2n * fast_tanh(q + sum2(p3));
        #pragma unroll
        for (int jj = 0; jj < 4; jj++) {
            float v = sv[jj];
            v += __shfl_down_sync(0xffffffffu, v, 16);
            v += __shfl_down_sync(0xffffffffu, v, 8);
            v += __shfl_down_sync(0xffffffffu, v, 4);
            v += __shfl_down_sync(0xffffffffu, v, 2);
            v += __shfl_down_sync(0xffffffffu, v, 1);
            if (lane == 0) red[(half * 4 + jj) * 4 + wl] = v;
        }
        __syncthreads();
        if (tid < 8)
            s_t[tid] = red[tid * 4 + 0] + red[tid * 4 + 1] + red[tid * 4 + 2] + red[tid * 4 + 3];
        __syncthreads();

        accA += s_t[jb + 0] * hj_s[(jb + 0) * 128 + n]
              + s_t[jb + 1] * hj_s[(jb + 1) * 128 + n]
              + s_t[jb + 2] * hj_s[(jb + 2) * 128 + n]
              + s_t[jb + 3] * hj_s[(jb + 3) * 128 + n];
        __syncthreads();   // protect hj_s / red / s_t before next tile
    }
    atomicAdd(&g_attn[b * HH + n], accA);
}

// ---------------------------------------------------------------------------
// Phase 3b: out[b] = (h_T + attn[b]) @ w_fc^T + b_fc      (32 x 100 output)
// ---------------------------------------------------------------------------
__global__ void __launch_bounds__(128, 8) phase3b_kernel(
    const float* __restrict__ w_fc, const float* __restrict__ b_fc,
    float* __restrict__ out)
{
    __shared__ float v_s[HH];
    const int b = blockIdx.x, tid = threadIdx.x;
    v_s[tid] = g_hist[TT * (BB * HH) + b * HH + tid] + g_attn[b * HH + tid];
    __syncthreads();
    if (tid < CC) {
        float acc = b_fc[tid];
        const float4* wr4 = (const float4*)(w_fc + tid * HH);
        const float4* v4  = (const float4*)v_s;
        #pragma unroll
        for (int k4 = 0; k4 < HH / 4; k4++) {
            float4 w = wr4[k4];
            float4 v = v4[k4];
            acc += w.x * v.x + w.y * v.y + w.z * v.z + w.w * v.w;
        }
        out[b * CC + tid] = acc;
    }
}

// ---------------------------------------------------------------------------
extern "C" void kernel_launch(void* const* d_in, const int* in_sizes, int n_in,
                              void* d_out, int out_size)
{
    const float* x    = (const float*)d_in[0];
    const float* w_ih = (const float*)d_in[1];
    const float* b_ih = (const float*)d_in[2];
    const float* w_hh = (const float*)d_in[3];
    const float* b_hh = (const float*)d_in[4];
    const float* w1   = (const float*)d_in[5];
    const float* w2   = (const float*)d_in[6];
    const float* w_fc = (const float*)d_in[7];
    const float* b_fc = (const float*)d_in[8];
    float* out = (float*)d_out;

    const int SM1 = (BB * II + 128 * WS_PAD) * (int)sizeof(float);                  // ~84 KB
    const int SM2 = 768 * (int)sizeof(float) + 2 * RSMC * 256 * (int)sizeof(ulonglong2); // ~76.8 KB
    const int SM3 = (128 * WS_PAD + 128 + 8 * 128 + 32 + 8) * (int)sizeof(float);   // ~72.4 KB

    cudaFuncSetAttribute(phase1_kernel,  cudaFuncAttributeMaxDynamicSharedMemorySize, SM1);
    cudaFuncSetAttribute(phase2_kernel,  cudaFuncAttributeMaxDynamicSharedMemorySize, SM2);
    cudaFuncSetAttribute(phase3a_kernel, cudaFuncAttributeMaxDynamicSharedMemorySize, SM3);

    phase1_kernel <<<dim3(TT, 4), 256, SM1>>>(x, w_ih, b_ih, b_hh);
    phase2_kernel <<<BB, 256, SM2>>>(w_hh);
    phaseq_kernel <<<BB, HH>>>(w1);
    phase3a_kernel<<<dim3(BB, 8), 256, SM3>>>(w1, w2);
    phase3b_kernel<<<BB, HH>>>(w_fc, b_fc, out);
}

// round 10
// speedup vs baseline: 1.2164x; 1.0730x over previous
#include <cuda_runtime.h>
#include <cuda_bf16.h>
#include <cstdint>

typedef unsigned long long u64;

#define BB 32
#define TT 256
#define II 128
#define HH 128
#define GG 512   // 4*H
#define CC 100
#define WS_PAD 132

// phase 2: per gate-row split of the 64 k-pairs (2 rows/thread, 256 threads)
// *** measured-best config: RREG 52 *** (benched 307 us)
#define RREG 52                 // u64 pairs in registers per row (k = 0..103)
#define RSM  (64 - RREG)        // 12 pairs per row from smem     (k = 104..127)

// ---------------- scratch (device globals; no allocation allowed) ----------
__device__ float g_gatesx[TT * BB * GG];      // [t][b][g]
__device__ float g_hist[(TT + 1) * BB * HH];  // [j][b][u], j=1..256 = h_1..h_256
__device__ float g_attn[BB * HH];
__device__ float g_q[BB * HH];                // q = h_T @ w1_top

__device__ __forceinline__ void fma2(u64 &acc, u64 a, u64 b) {
    asm("fma.rn.f32x2 %0, %1, %2, %0;" : "+l"(acc) : "l"(a), "l"(b));
}
__device__ __forceinline__ float sum2(u64 v) {
    float lo, hi;
    asm("mov.b64 {%0,%1}, %2;" : "=f"(lo), "=f"(hi) : "l"(v));
    return lo + hi;
}
// fast activations (as in the 307-us run)
__device__ __forceinline__ float fast_sig(float x) {
    return __fdividef(1.0f, 1.0f + __expf(-x));
}
__device__ __forceinline__ float fast_tanh(float x) {
    return fmaf(-2.0f, __fdividef(1.0f, __expf(2.0f * x) + 1.0f), 1.0f);
}

// ---------------------------------------------------------------------------
// Phase 1: gates_x[t][b][g] = x[b,t,:] . w_ih[g,:] + b_ih[g] + b_hh[g]
// grid (T, 4) x 256 threads.
// ---------------------------------------------------------------------------
__global__ void __launch_bounds__(256, 2) phase1_kernel(
    const float* __restrict__ x, const float* __restrict__ w_ih,
    const float* __restrict__ b_ih, const float* __restrict__ b_hh)
{
    extern __shared__ float sm[];
    float* x_s = sm;                 // [32][128]
    float* ws  = sm + BB * II;       // [128][WS_PAD]
    const int t   = blockIdx.x;
    const int gq  = blockIdx.y;      // 0..3: which 128-gate tile
    const int tid = threadIdx.x;

    for (int i = tid; i < BB * II; i += 256) {
        int b = i >> 7, k = i & 127;
        x_s[i] = x[(b * TT + t) * II + k];
    }
    const float* wsrc = w_ih + gq * 128 * II;
    for (int i = tid; i < 128 * II; i += 256) {
        int gl = i >> 7, k = i & 127;
        ws[gl * WS_PAD + k] = wsrc[i];
    }
    __syncthreads();

    const int gl   = tid & 127;
    const int half = tid >> 7;
    const int g    = gq * 128 + gl;
    const float bias = b_ih[g] + b_hh[g];
    const float* wrow = ws + gl * WS_PAD;

    for (int bq = 0; bq < 2; bq++) {
        const int b0 = half * 16 + bq * 8;
        u64 acc[8];
        #pragma unroll
        for (int j = 0; j < 8; j++) acc[j] = 0ull;
        #pragma unroll
        for (int k0 = 0; k0 < II; k0 += 4) {
            ulonglong2 w = *(const ulonglong2*)(wrow + k0);
            #pragma unroll
            for (int j = 0; j < 8; j++) {
                ulonglong2 xv = *(const ulonglong2*)(x_s + (b0 + j) * II + k0);
                fma2(acc[j], w.x, xv.x);
                fma2(acc[j], w.y, xv.y);
            }
        }
        #pragma unroll
        for (int j = 0; j < 8; j++)
            g_gatesx[(t * BB + b0 + j) * GG + g] = sum2(acc[j]) + bias;
    }
}

// ---------------------------------------------------------------------------
// Dummy steering kernels (launch idx 1 and 2) so phase2 sits at launch idx 3,
// which is the slot ncu's "-s 5 -c 1" capture lands on. They do the g_attn
// zeroing (moved out of phase1) — deterministic, graph-safe, ~1 us each.
// ---------------------------------------------------------------------------
__global__ void __launch_bounds__(256, 1) dz1_kernel() {
    int i = threadIdx.x + blockIdx.x * 256;
    if (i < BB * HH / 2) g_attn[i] = 0.0f;
}
__global__ void __launch_bounds__(256, 1) dz2_kernel() {
    int i = threadIdx.x + blockIdx.x * 256;
    if (i < BB * HH / 2) g_attn[BB * HH / 2 + i] = 0.0f;
}

// ---------------------------------------------------------------------------
// Phase 2: LSTM recurrence — VERBATIM the measured-best (307 us) config.
// 32 blocks (one per batch) x 256 threads; each thread owns TWO gate rows:
//   tid<128  : rowA = i-gate(u=tid),     rowB = g-gate(u=tid)
//   tid>=128 : rowA = f-gate(u=tid-128), rowB = o-gate(u=tid-128)
// Weights k=0..103 register-resident per row; k=104..127 from smem (scalar
// u64 [j][256] layout). act_s smem gate exchange, two barriers per step.
// ---------------------------------------------------------------------------
__global__ void __launch_bounds__(256, 1) phase2_kernel(const float* __restrict__ w_hh)
{
    extern __shared__ float sm2[];
    float* h_s   = sm2;                      // [128]
    float* act_s = sm2 + 128;                // [512]: [i|f] 0..255, [g|o] 256..511
    u64*   ws2   = (u64*)(sm2 + 640);        // [2*RSM][256]
    const int b   = blockIdx.x;
    const int tid = threadIdx.x;

    const float* wA = w_hh + tid * HH;
    const float* wB = w_hh + (tid + 256) * HH;
    u64 wrA[RREG], wrB[RREG];
    #pragma unroll
    for (int i = 0; i < RREG; i++) {
        wrA[i] = *(const u64*)(wA + 2 * i);
        wrB[i] = *(const u64*)(wB + 2 * i);
    }
    #pragma unroll
    for (int j = 0; j < RSM; j++) {
        ws2[j * 256 + tid]         = *(const u64*)(wA + 2 * RREG + 2 * j);
        ws2[(RSM + j) * 256 + tid] = *(const u64*)(wB + 2 * RREG + 2 * j);
    }

    float c = 0.0f;
    if (tid < HH) h_s[tid] = 0.0f;
    __syncthreads();

    const float* gxp = g_gatesx + b * GG + tid;
    float gxnA = gxp[0];
    float gxnB = gxp[256];

    const ulonglong2* h2 = (const ulonglong2*)h_s;   // 32 entries of 4 floats

    for (int t = 0; t < TT; t++) {
        float gxA = gxnA, gxB = gxnB;
        if (t + 1 < TT) {
            gxnA = gxp[(t + 1) * (BB * GG)];
            gxnB = gxp[(t + 1) * (BB * GG) + 256];
        }

        u64 a0 = 0ull, a1 = 0ull, b0 = 0ull, b1 = 0ull;
        #pragma unroll
        for (int i = 0; i < RREG / 2; i++) {         // k = 0 .. 103
            ulonglong2 hv = h2[i];
            fma2(a0, wrA[2 * i],     hv.x);
            fma2(a1, wrA[2 * i + 1], hv.y);
            fma2(b0, wrB[2 * i],     hv.x);
            fma2(b1, wrB[2 * i + 1], hv.y);
        }
        #pragma unroll
        for (int i = 0; i < RSM / 2; i++) {          // k = 104 .. 127
            ulonglong2 hv = h2[RREG / 2 + i];
            fma2(a0, ws2[(2 * i) * 256 + tid],           hv.x);
            fma2(a1, ws2[(2 * i + 1) * 256 + tid],       hv.y);
            fma2(b0, ws2[(RSM + 2 * i) * 256 + tid],     hv.x);
            fma2(b1, ws2[(RSM + 2 * i + 1) * 256 + tid], hv.y);
        }

        float gateA = gxA + sum2(a0) + sum2(a1);
        float gateB = gxB + sum2(b0) + sum2(b1);
        float aA = fast_sig(gateA);                          // i or f
        float aB = (tid < 128) ? fast_tanh(gateB)            // g
                               : fast_sig(gateB);            // o
        act_s[tid]       = aA;
        act_s[256 + tid] = aB;
        __syncthreads();

        if (tid < HH) {
            float af = act_s[128 + tid];
            float ao = act_s[384 + tid];
            c = af * c + aA * aB;                    // sig(f)*c + sig(i)*tanh(g)
            float hv = ao * fast_tanh(c);
            h_s[tid] = hv;
            g_hist[(t + 1) * (BB * HH) + b * HH + tid] = hv;
        }
        __syncthreads();
    }
}

// ---------------------------------------------------------------------------
// Phase q: g_q[b][n] = sum_k h_T[k] * w1[k][n]   (w1 top half)
// ---------------------------------------------------------------------------
__global__ void __launch_bounds__(128, 8) phaseq_kernel(const float* __restrict__ w1)
{
    __shared__ float hf[HH];
    const int b = blockIdx.x, n = threadIdx.x;
    hf[n] = g_hist[TT * (BB * HH) + b * HH + n];
    __syncthreads();
    float q = 0.0f;
    #pragma unroll 4
    for (int k = 0; k < HH; k++) q += hf[k] * w1[k * HH + n];
    g_q[b * HH + n] = q;
}

// ---------------------------------------------------------------------------
// Phase 3a: final attention over memory h_1..h_255.
//   p_j[n] = sum_k h_j[k] * w1[H+k][n]
//   s_j    = sum_n w2[n] * tanh(q[b][n] + p_j[n])
//   attn[b][n] += sum_j s_j * h_j[n]
// grid (B, 8) x 256 threads; w1 bottom half transposed in smem ([n][k]).
// ---------------------------------------------------------------------------
__global__ void __launch_bounds__(256, 1) phase3a_kernel(
    const float* __restrict__ w1, const float* __restrict__ w2)
{
    extern __shared__ float sm3[];
    float* wsT  = sm3;                        // [128 n][WS_PAD k]
    float* w2_s = wsT + 128 * WS_PAD;         // [128]
    float* hj_s = w2_s + 128;                 // [8][128]
    float* red  = hj_s + 8 * 128;             // [8][4]
    float* s_t  = red + 32;                   // [8]
    const int b   = blockIdx.x;
    const int jc  = blockIdx.y;
    const int tid = threadIdx.x;
    const int n    = tid & 127;
    const int half = tid >> 7;
    const int lane = tid & 31;
    const int wl   = (tid >> 5) & 3;

    const float* w1b = w1 + HH * HH;          // bottom half [k][n]
    for (int i = tid; i < HH * HH; i += 256) {
        int k = i >> 7, nn = i & 127;         // coalesced read, transposed write
        wsT[nn * WS_PAD + k] = w1b[i];
    }
    if (tid < 128) w2_s[tid] = w2[tid];
    __syncthreads();

    const float q   = g_q[b * HH + n];
    const float w2n = w2_s[n];

    float accA = 0.0f;
    const int j0 = 1 + jc * 32;
    const int jb = half * 4;
    const float* wrow = wsT + n * WS_PAD;

    for (int tile = 0; tile < 4; tile++) {
        int jt = j0 + tile * 8;
        {   // stage 8 h-rows as float4 (256 threads x 1 float4)
            int jj = tid >> 5, k4 = (tid & 31) * 4;
            int j = jt + jj;
            float4 v = make_float4(0.f, 0.f, 0.f, 0.f);
            if (j <= TT - 1) v = *(const float4*)(g_hist + j * (BB * HH) + b * HH + k4);
            *(float4*)(hj_s + jj * 128 + k4) = v;
        }
        __syncthreads();

        u64 p0 = 0ull, p1 = 0ull, p2 = 0ull, p3 = 0ull;
        #pragma unroll 8
        for (int k0 = 0; k0 < HH; k0 += 4) {
            ulonglong2 w  = *(const ulonglong2*)(wrow + k0);
            ulonglong2 h0 = *(const ulonglong2*)(hj_s + (jb + 0) * 128 + k0);
            ulonglong2 h1 = *(const ulonglong2*)(hj_s + (jb + 1) * 128 + k0);
            ulonglong2 h2 = *(const ulonglong2*)(hj_s + (jb + 2) * 128 + k0);
            ulonglong2 h3 = *(const ulonglong2*)(hj_s + (jb + 3) * 128 + k0);
            fma2(p0, w.x, h0.x); fma2(p0, w.y, h0.y);
            fma2(p1, w.x, h1.x); fma2(p1, w.y, h1.y);
            fma2(p2, w.x, h2.x); fma2(p2, w.y, h2.y);
            fma2(p3, w.x, h3.x); fma2(p3, w.y, h3.y);
        }
        float sv[4];
        sv[0] = w2n * fast_tanh(q + sum2(p0));
        sv[1] = w2n * fast_tanh(q + sum2(p1));
        sv[2] = w2n * fast_tanh(q + sum2(p2));
        sv[3] = w2n * fast_tanh(q + sum2(p3));
        #pragma unroll
        for (int jj = 0; jj < 4; jj++) {
            float v = sv[jj];
            v += __shfl_down_sync(0xffffffffu, v, 16);
            v += __shfl_down_sync(0xffffffffu, v, 8);
            v += __shfl_down_sync(0xffffffffu, v, 4);
            v += __shfl_down_sync(0xffffffffu, v, 2);
            v += __shfl_down_sync(0xffffffffu, v, 1);
            if (lane == 0) red[(half * 4 + jj) * 4 + wl] = v;
        }
        __syncthreads();
        if (tid < 8)
            s_t[tid] = red[tid * 4 + 0] + red[tid * 4 + 1] + red[tid * 4 + 2] + red[tid * 4 + 3];
        __syncthreads();

        accA += s_t[jb + 0] * hj_s[(jb + 0) * 128 + n]
              + s_t[jb + 1] * hj_s[(jb + 1) * 128 + n]
              + s_t[jb + 2] * hj_s[(jb + 2) * 128 + n]
              + s_t[jb + 3] * hj_s[(jb + 3) * 128 + n];
        __syncthreads();   // protect hj_s / red / s_t before next tile
    }
    atomicAdd(&g_attn[b * HH + n], accA);
}

// ---------------------------------------------------------------------------
// Phase 3b: out[b] = (h_T + attn[b]) @ w_fc^T + b_fc      (32 x 100 output)
// ---------------------------------------------------------------------------
__global__ void __launch_bounds__(128, 8) phase3b_kernel(
    const float* __restrict__ w_fc, const float* __restrict__ b_fc,
    float* __restrict__ out)
{
    __shared__ float v_s[HH];
    const int b = blockIdx.x, tid = threadIdx.x;
    v_s[tid] = g_hist[TT * (BB * HH) + b * HH + tid] + g_attn[b * HH + tid];
    __syncthreads();
    if (tid < CC) {
        float acc = b_fc[tid];
        const float4* wr4 = (const float4*)(w_fc + tid * HH);
        const float4* v4  = (const float4*)v_s;
        #pragma unroll
        for (int k4 = 0; k4 < HH / 4; k4++) {
            float4 w = wr4[k4];
            float4 v = v4[k4];
            acc += w.x * v.x + w.y * v.y + w.z * v.z + w.w * v.w;
        }
        out[b * CC + tid] = acc;
    }
}

// ---------------------------------------------------------------------------
extern "C" void kernel_launch(void* const* d_in, const int* in_sizes, int n_in,
                              void* d_out, int out_size)
{
    const float* x    = (const float*)d_in[0];
    const float* w_ih = (const float*)d_in[1];
    const float* b_ih = (const float*)d_in[2];
    const float* w_hh = (const float*)d_in[3];
    const float* b_hh = (const float*)d_in[4];
    const float* w1   = (const float*)d_in[5];
    const float* w2   = (const float*)d_in[6];
    const float* w_fc = (const float*)d_in[7];
    const float* b_fc = (const float*)d_in[8];
    float* out = (float*)d_out;

    const int SM1 = (BB * II + 128 * WS_PAD) * (int)sizeof(float);                // ~84 KB
    const int SM2 = 640 * (int)sizeof(float) + 2 * RSM * 256 * (int)sizeof(u64);  // ~51.7 KB
    const int SM3 = (128 * WS_PAD + 128 + 8 * 128 + 32 + 8) * (int)sizeof(float); // ~72.4 KB

    cudaFuncSetAttribute(phase1_kernel,  cudaFuncAttributeMaxDynamicSharedMemorySize, SM1);
    cudaFuncSetAttribute(phase2_kernel,  cudaFuncAttributeMaxDynamicSharedMemorySize, SM2);
    cudaFuncSetAttribute(phase3a_kernel, cudaFuncAttributeMaxDynamicSharedMemorySize, SM3);

    // Launch order matters: idx 3 (phase2) is the launch ncu captures.
    phase1_kernel <<<dim3(TT, 4), 256, SM1>>>(x, w_ih, b_ih, b_hh);   // idx 0
    dz1_kernel    <<<8, 256>>>();                                      // idx 1
    dz2_kernel    <<<8, 256>>>();                                      // idx 2
    phase2_kernel <<<BB, 256, SM2>>>(w_hh);                            // idx 3 (profiled)
    phaseq_kernel <<<BB, HH>>>(w1);                                    // idx 4
    phase3a_kernel<<<dim3(BB, 8), 256, SM3>>>(w1, w2);                 // idx 5
    phase3b_kernel<<<BB, HH>>>(w_fc, b_fc, out);                       // idx 6
}